// round 4
// baseline (speedup 1.0000x reference)
#include <cuda_runtime.h>
#include <cstdint>

// ---------------------------------------------------------------------------
// Problem constants
// ---------------------------------------------------------------------------
#define NHEAD   12
#define HD      64
#define NTOK    512
#define NBATCH  32
#define DIM     768
#define MTOK    (NBATCH * NTOK)        // 16384
#define QKV_N   (3 * DIM)              // 2304
#define ATTN_SCALE 0.125f              // 64^-0.5

// ---------------------------------------------------------------------------
// Scratch (static __device__ arrays -- no allocation allowed)
// ---------------------------------------------------------------------------
__device__ float g_q[(size_t)NBATCH * NHEAD * NTOK * HD];
__device__ float g_k[(size_t)NBATCH * NHEAD * NTOK * HD];
__device__ float g_v[(size_t)NBATCH * NHEAD * NTOK * HD];
__device__ float g_bias[(size_t)NHEAD * NTOK * NTOK];           // [h][n][m]
__device__ float g_attnout[(size_t)MTOK * DIM];

// ---------------------------------------------------------------------------
// Helpers: tf32 round + mma.sync m16n8k8 tf32
// ---------------------------------------------------------------------------
__device__ __forceinline__ uint32_t f2tf32(float x) {
    uint32_t r;
    asm("cvt.rna.tf32.f32 %0, %1;" : "=r"(r) : "f"(x));
    return r;
}

__device__ __forceinline__ void mma_tf32(float* c, const uint32_t* a,
                                         const uint32_t* b) {
    asm volatile(
        "mma.sync.aligned.m16n8k8.row.col.f32.tf32.tf32.f32 "
        "{%0,%1,%2,%3}, {%4,%5,%6,%7}, {%8,%9}, {%0,%1,%2,%3};"
        : "+f"(c[0]), "+f"(c[1]), "+f"(c[2]), "+f"(c[3])
        : "r"(a[0]), "r"(a[1]), "r"(a[2]), "r"(a[3]),
          "r"(b[0]), "r"(b[1]));
}

// ---------------------------------------------------------------------------
// Kernel 1: expand relative-position bias table -> g_bias[h][n][m]
// ---------------------------------------------------------------------------
__global__ void bias_gather_kernel(const float* __restrict__ table,
                                   const int*   __restrict__ idx)
{
    int e = blockIdx.x * 256 + threadIdx.x;
    int id = idx[e];
    const float* t = table + (size_t)id * NHEAD;
#pragma unroll
    for (int h = 0; h < NHEAD; h++)
        g_bias[(size_t)h * NTOK * NTOK + e] = t[h];
}

// ---------------------------------------------------------------------------
// Kernel 2/4: TF32 tensor-core GEMM.  C = A @ Bw^T + bias.
// A [M,K] row-major, Bw [Nn,K] row-major. BM=BN=128, BK=32, 256 thr = 8 warps
// (4 m-warps x 2 n-warps, each 32x64). Smem tiles stored fragment-permuted:
//   A frag (m16n8k8): t=(r%8)*4+(k%4), reg=(r%16)/8 + 2*((k%8)/4)
//     As[((mt*4+ks)*32 + t)*4 + reg],  mt=r/16, ks=k/8   -> LDS.128 in loop
//   B frag: t=(n%8)*4+(k%4), reg=(k%8)/4
//     Bs[((nt*4+ks)*32 + t)*2 + reg],  nt=n/8,  ks=k/8   -> LDS.64 in loop
// MODE 1: A = x, scatter epilogue into g_q/g_k/g_v (q pre-scaled)
// MODE 0: A = g_attnout, epilogue -> Cout
// ---------------------------------------------------------------------------
template <int MODE>
__global__ __launch_bounds__(256, 2)
void gemm_tf32_kernel(const float* __restrict__ Ain,
                      const float* __restrict__ Bw,
                      const float* __restrict__ biasv,
                      float* __restrict__ Cout,
                      int M, int Nn, int K)
{
    __shared__ uint32_t As[4096];   // 16 KB
    __shared__ uint32_t Bs[4096];   // 16 KB

    const float* A = (MODE == 0) ? g_attnout : Ain;

    const int tid  = threadIdx.x;
    const int warp = tid >> 5;
    const int lane = tid & 31;
    const int wm   = warp & 3;      // 0..3  -> 32-row slab
    const int wn   = warp >> 2;     // 0..1  -> 64-col slab
    const int m0   = blockIdx.y * 128;
    const int n0   = blockIdx.x * 128;

    float acc[2][8][4];
#pragma unroll
    for (int i = 0; i < 2; i++)
#pragma unroll
        for (int j = 0; j < 8; j++)
#pragma unroll
            for (int r = 0; r < 4; r++) acc[i][j][r] = 0.0f;

    for (int kt = 0; kt < K; kt += 32) {
        // ---- fill permuted tiles (each thread: 4 float4 from A, 4 from Bw) --
#pragma unroll
        for (int u = 0; u < 4; u++) {
            int f4  = tid + 256 * u;          // 0..1023
            int row = f4 >> 3;                // 0..127
            int kq  = f4 & 7;                 // k4-group: k = kq*4
            int ks  = kq >> 1;                // k/8
            int kh  = kq & 1;                 // (k%8)/4

            float4 av = *(const float4*)&A[(size_t)(m0 + row) * K + kt + kq * 4];
            {
                int mt   = row >> 4;
                int r8   = (row >> 3) & 1;
                int reg  = r8 + 2 * kh;
                int base = ((mt * 4 + ks) * 32 + ((row & 7) << 2)) * 4 + reg;
                As[base + 0]  = f2tf32(av.x);
                As[base + 4]  = f2tf32(av.y);
                As[base + 8]  = f2tf32(av.z);
                As[base + 12] = f2tf32(av.w);
            }
            float4 bv = *(const float4*)&Bw[(size_t)(n0 + row) * K + kt + kq * 4];
            {
                int nt   = row >> 3;
                int base = ((nt * 4 + ks) * 32 + ((row & 7) << 2)) * 2 + kh;
                Bs[base + 0] = f2tf32(bv.x);
                Bs[base + 2] = f2tf32(bv.y);
                Bs[base + 4] = f2tf32(bv.z);
                Bs[base + 6] = f2tf32(bv.w);
            }
        }
        __syncthreads();

        // ---- mainloop: 4 k-steps x (2 m-tiles x 8 n-tiles) mma ----
#pragma unroll
        for (int ks = 0; ks < 4; ks++) {
            uint32_t afr[2][4];
#pragma unroll
            for (int mt2 = 0; mt2 < 2; mt2++) {
                int mt = wm * 2 + mt2;
                *(uint4*)afr[mt2] =
                    *(const uint4*)&As[((mt * 4 + ks) * 32 + lane) * 4];
            }
#pragma unroll
            for (int nt2 = 0; nt2 < 8; nt2++) {
                int nt = wn * 8 + nt2;
                uint32_t bfr[2];
                *(uint2*)bfr = *(const uint2*)&Bs[((nt * 4 + ks) * 32 + lane) * 2];
                mma_tf32(acc[0][nt2], afr[0], bfr);
                mma_tf32(acc[1][nt2], afr[1], bfr);
            }
        }
        __syncthreads();
    }

    // ---- epilogue ----
    const int gr = lane >> 2;           // groupID
    const int gl = lane & 3;            // thread in group
#pragma unroll
    for (int mt2 = 0; mt2 < 2; mt2++) {
#pragma unroll
        for (int nt2 = 0; nt2 < 8; nt2++) {
            int n  = n0 + wn * 64 + nt2 * 8 + gl * 2;
            float b0 = biasv[n], b1 = biasv[n + 1];
#pragma unroll
            for (int half = 0; half < 2; half++) {
                int m = m0 + wm * 32 + mt2 * 16 + gr + half * 8;
                float v0 = acc[mt2][nt2][half * 2 + 0] + b0;
                float v1 = acc[mt2][nt2][half * 2 + 1] + b1;
                if (MODE == 0) {
                    *(float2*)&Cout[(size_t)m * Nn + n] = make_float2(v0, v1);
                } else {
                    int part = n / DIM;
                    int rem  = n - part * DIM;
                    int h    = rem >> 6;
                    int d    = rem & 63;
                    int bb   = m >> 9;
                    int tok  = m & 511;
                    size_t o = ((size_t)((bb * NHEAD + h) * NTOK + tok)) * HD + d;
                    if (part == 0) {
                        *(float2*)&g_q[o] =
                            make_float2(v0 * ATTN_SCALE, v1 * ATTN_SCALE);
                    } else if (part == 1) {
                        *(float2*)&g_k[o] = make_float2(v0, v1);
                    } else {
                        *(float2*)&g_v[o] = make_float2(v0, v1);
                    }
                }
            }
        }
    }
}

// ---------------------------------------------------------------------------
// Kernel 3: fused flash-style attention (fp32 SIMT), unchanged from R2.
// ---------------------------------------------------------------------------
#define CH 32
#define NCHUNK (NTOK / CH)

__global__ __launch_bounds__(256)
void attn_kernel()
{
    __shared__ float Qt[64 * 64];
    __shared__ float KV[CH * 64];
    __shared__ float St[CH * 64];
    __shared__ float mpart[4 * 64];
    __shared__ float spart[4 * 64];
    __shared__ float m_run[64];
    __shared__ float s_run[64];
    __shared__ float fsc[64];

    const int tid = threadIdx.x;
    const int tx  = tid & 15;
    const int ty  = tid >> 4;
    const int row0 = blockIdx.x * 64;
    const int h    = blockIdx.y;
    const int b    = blockIdx.z;
    const size_t base = ((size_t)(b * NHEAD + h)) * NTOK * HD;

    {
        int r    = tid & 63;
        int dblk = tid >> 6;
#pragma unroll
        for (int u = 0; u < 4; u++) {
            int d4 = dblk * 16 + u * 4;
            float4 q = *(const float4*)&g_q[base + (size_t)(row0 + r) * HD + d4];
            Qt[(d4 + 0) * 64 + r] = q.x;
            Qt[(d4 + 1) * 64 + r] = q.y;
            Qt[(d4 + 2) * 64 + r] = q.z;
            Qt[(d4 + 3) * 64 + r] = q.w;
        }
    }
    if (tid < 64) { m_run[tid] = -1e30f; s_run[tid] = 0.0f; }

    float oacc[4][4];
#pragma unroll
    for (int i = 0; i < 4; i++)
#pragma unroll
        for (int j = 0; j < 4; j++) oacc[i][j] = 0.0f;

    const int rs  = tid & 63;
    const int sub = tid >> 6;
    const float* brow = &g_bias[((size_t)h * NTOK + row0 + rs) * NTOK];

    for (int ch = 0; ch < NCHUNK; ch++) {
        const int c0 = ch * CH;
        __syncthreads();

#pragma unroll
        for (int u = 0; u < 2; u++) {
            int f  = tid + 256 * u;
            int c  = f >> 4;
            int d4 = (f & 15) * 4;
            *(float4*)&KV[c * 64 + d4] =
                *(const float4*)&g_k[base + (size_t)(c0 + c) * HD + d4];
        }
        __syncthreads();

        {
            float sacc[2][4];
#pragma unroll
            for (int i = 0; i < 2; i++)
#pragma unroll
                for (int j = 0; j < 4; j++) sacc[i][j] = 0.0f;

#pragma unroll 8
            for (int d = 0; d < 64; d++) {
                float a0 = KV[(2 * ty + 0) * 64 + d];
                float a1 = KV[(2 * ty + 1) * 64 + d];
                float4 bq = *(const float4*)&Qt[d * 64 + 4 * tx];
                sacc[0][0] = fmaf(a0, bq.x, sacc[0][0]);
                sacc[0][1] = fmaf(a0, bq.y, sacc[0][1]);
                sacc[0][2] = fmaf(a0, bq.z, sacc[0][2]);
                sacc[0][3] = fmaf(a0, bq.w, sacc[0][3]);
                sacc[1][0] = fmaf(a1, bq.x, sacc[1][0]);
                sacc[1][1] = fmaf(a1, bq.y, sacc[1][1]);
                sacc[1][2] = fmaf(a1, bq.z, sacc[1][2]);
                sacc[1][3] = fmaf(a1, bq.w, sacc[1][3]);
            }
#pragma unroll
            for (int i = 0; i < 2; i++)
                *(float4*)&St[(2 * ty + i) * 64 + 4 * tx] =
                    make_float4(sacc[i][0], sacc[i][1], sacc[i][2], sacc[i][3]);
        }
        __syncthreads();

#pragma unroll
        for (int u = 0; u < 2; u++) {
            int f  = tid + 256 * u;
            int c  = f >> 4;
            int d4 = (f & 15) * 4;
            *(float4*)&KV[c * 64 + d4] =
                *(const float4*)&g_v[base + (size_t)(c0 + c) * HD + d4];
        }

        {
            float mp = -1e30f;
#pragma unroll
            for (int cc = 0; cc < 8; cc++) {
                int c = sub * 8 + cc;
                float x = St[c * 64 + rs] + brow[c0 + c];
                St[c * 64 + rs] = x;
                mp = fmaxf(mp, x);
            }
            mpart[sub * 64 + rs] = mp;
        }
        __syncthreads();

        if (tid < 64) {
            float m_old = m_run[tid];
            float mc = fmaxf(fmaxf(mpart[tid], mpart[64 + tid]),
                             fmaxf(mpart[128 + tid], mpart[192 + tid]));
            float mn = fmaxf(m_old, mc);
            m_run[tid] = mn;
            fsc[tid] = __expf(m_old - mn);
        }
        __syncthreads();

        {
            float mn = m_run[rs];
            float sp = 0.0f;
#pragma unroll
            for (int cc = 0; cc < 8; cc++) {
                int c = sub * 8 + cc;
                float e = __expf(St[c * 64 + rs] - mn);
                St[c * 64 + rs] = e;
                sp += e;
            }
            spart[sub * 64 + rs] = sp;
        }
        __syncthreads();

        if (tid < 64)
            s_run[tid] = s_run[tid] * fsc[tid] +
                         (spart[tid] + spart[64 + tid] +
                          spart[128 + tid] + spart[192 + tid]);

        {
            float f0 = fsc[4 * ty + 0];
            float f1 = fsc[4 * ty + 1];
            float f2 = fsc[4 * ty + 2];
            float f3 = fsc[4 * ty + 3];
#pragma unroll
            for (int j = 0; j < 4; j++) {
                oacc[0][j] *= f0; oacc[1][j] *= f1;
                oacc[2][j] *= f2; oacc[3][j] *= f3;
            }
#pragma unroll 8
            for (int kk = 0; kk < CH; kk++) {
                float4 p = *(const float4*)&St[kk * 64 + 4 * ty];
                float4 v = *(const float4*)&KV[kk * 64 + 4 * tx];
                oacc[0][0] = fmaf(p.x, v.x, oacc[0][0]);
                oacc[0][1] = fmaf(p.x, v.y, oacc[0][1]);
                oacc[0][2] = fmaf(p.x, v.z, oacc[0][2]);
                oacc[0][3] = fmaf(p.x, v.w, oacc[0][3]);
                oacc[1][0] = fmaf(p.y, v.x, oacc[1][0]);
                oacc[1][1] = fmaf(p.y, v.y, oacc[1][1]);
                oacc[1][2] = fmaf(p.y, v.z, oacc[1][2]);
                oacc[1][3] = fmaf(p.y, v.w, oacc[1][3]);
                oacc[2][0] = fmaf(p.z, v.x, oacc[2][0]);
                oacc[2][1] = fmaf(p.z, v.y, oacc[2][1]);
                oacc[2][2] = fmaf(p.z, v.z, oacc[2][2]);
                oacc[2][3] = fmaf(p.z, v.w, oacc[2][3]);
                oacc[3][0] = fmaf(p.w, v.x, oacc[3][0]);
                oacc[3][1] = fmaf(p.w, v.y, oacc[3][1]);
                oacc[3][2] = fmaf(p.w, v.z, oacc[3][2]);
                oacc[3][3] = fmaf(p.w, v.w, oacc[3][3]);
            }
        }
    }
    __syncthreads();

#pragma unroll
    for (int i = 0; i < 4; i++) {
        int r = 4 * ty + i;
        float inv = 1.0f / s_run[r];
        float4 o = make_float4(oacc[i][0] * inv, oacc[i][1] * inv,
                               oacc[i][2] * inv, oacc[i][3] * inv);
        *(float4*)&g_attnout[((size_t)b * NTOK + row0 + r) * DIM + h * HD + 4 * tx] = o;
    }
}

// ---------------------------------------------------------------------------
// Launch (kernel launches only -- fully graph-capturable)
// ---------------------------------------------------------------------------
extern "C" void kernel_launch(void* const* d_in, const int* in_sizes, int n_in,
                              void* d_out, int out_size)
{
    const float* x     = (const float*)d_in[0];
    const float* Wqkv  = (const float*)d_in[1];
    const float* bqkv  = (const float*)d_in[2];
    const float* table = (const float*)d_in[3];
    const int*   idx   = (const int*)  d_in[4];
    const float* Wproj = (const float*)d_in[5];
    const float* bproj = (const float*)d_in[6];
    float* out = (float*)d_out;

    bias_gather_kernel<<<(NTOK * NTOK) / 256, 256>>>(table, idx);

    gemm_tf32_kernel<1><<<dim3(QKV_N / 128, MTOK / 128), 256>>>(
        x, Wqkv, bqkv, nullptr, MTOK, QKV_N, DIM);

    attn_kernel<<<dim3(NTOK / 64, NHEAD, NBATCH), 256>>>();

    gemm_tf32_kernel<0><<<dim3(DIM / 128, MTOK / 128), 256>>>(
        nullptr, Wproj, bproj, out, MTOK, DIM, DIM);
}

// round 5
// speedup vs baseline: 3.2067x; 3.2067x over previous
#include <cuda_runtime.h>
#include <cstdint>

#define NHEAD 12
#define HD 64
#define NTOK 512
#define NBATCH 32
#define DIM 768
#define MTOK (NBATCH*NTOK)
#define QKV_N (3*DIM)
#define ATTN_SCALE 0.125f

__device__ float g_q[(size_t)NBATCH*NHEAD*NTOK*HD];
__device__ float g_k[(size_t)NBATCH*NHEAD*NTOK*HD];
__device__ float g_v[(size_t)NBATCH*NHEAD*NTOK*HD];
__device__ float g_biasp[(size_t)NHEAD*NTOK*NTOK];   // c-frag layout [h][rt][ch][nt][lane][reg]
__device__ float g_attnout[(size_t)MTOK*DIM];

__device__ __forceinline__ uint32_t f2tf32(float x){
    uint32_t r; asm("cvt.rna.tf32.f32 %0, %1;" : "=r"(r) : "f"(x)); return r;
}
__device__ __forceinline__ void mma_tf32(float* c,const uint32_t* a,const uint32_t* b){
    asm volatile("mma.sync.aligned.m16n8k8.row.col.f32.tf32.tf32.f32 "
        "{%0,%1,%2,%3}, {%4,%5,%6,%7}, {%8,%9}, {%0,%1,%2,%3};"
        : "+f"(c[0]),"+f"(c[1]),"+f"(c[2]),"+f"(c[3])
        : "r"(a[0]),"r"(a[1]),"r"(a[2]),"r"(a[3]),"r"(b[0]),"r"(b[1]));
}

// ---- bias gather into c-fragment layout ----
__global__ void bias_gather_kernel(const float* __restrict__ table,
                                   const int* __restrict__ idx)
{
    int e = blockIdx.x*256 + threadIdx.x;       // 0..262143
    int rt=e>>13, kt=(e>>10)&7, nt=(e>>7)&7, lane=(e>>2)&31, reg=e&3;
    int g=lane>>2, l=lane&3;
    int row = rt*16 + g + 8*(reg>>1);
    int col = kt*64 + nt*8 + 2*l + (reg&1);
    int id = idx[row*NTOK + col];
    const float* t = table + (size_t)id*NHEAD;
#pragma unroll
    for (int h=0; h<NHEAD; h++)
        g_biasp[(size_t)h*262144 + e] = t[h];
}

// ---- TF32 GEMM: C = A @ Bw^T + bias, swizzled frag tiles ----
template<int MODE>
__global__ __launch_bounds__(256,2)
void gemm_tf32_kernel(const float* __restrict__ Ain,const float* __restrict__ Bw,
                      const float* __restrict__ biasv,float* __restrict__ Cout,
                      int M,int Nn,int K)
{
    __shared__ uint32_t As[4096];
    __shared__ uint32_t Bs[4096];
    const float* A = (MODE==0) ? g_attnout : Ain;
    const int tid=threadIdx.x, warp=tid>>5, lane=tid&31;
    const int wm=warp&3, wn=warp>>2;
    const int m0=blockIdx.y*128, n0=blockIdx.x*128;

    float acc[2][8][4];
#pragma unroll
    for(int i=0;i<2;i++)
#pragma unroll
        for(int j=0;j<8;j++)
#pragma unroll
            for(int r=0;r<4;r++) acc[i][j][r]=0.f;

    for (int kt=0; kt<K; kt+=32) {
#pragma unroll
        for (int u=0; u<4; u++) {
            int f4=tid+256*u, row=f4>>3, kq=f4&7, ks=kq>>1, kh=kq&1, g=row&7;
            float4 av = *(const float4*)&A[(size_t)(m0+row)*K + kt + kq*4];
            {
                int mt=row>>4, r8=(row>>3)&1;
                int sg=(ks^(g>>1))&3;
                int ab=((mt*4+ks)*32+4*g)*4 + r8 + 2*kh;
                As[ab+((0^sg)<<2)]=f2tf32(av.x);
                As[ab+((1^sg)<<2)]=f2tf32(av.y);
                As[ab+((2^sg)<<2)]=f2tf32(av.z);
                As[ab+((3^sg)<<2)]=f2tf32(av.w);
            }
            float4 bv = *(const float4*)&Bw[(size_t)(n0+row)*K + kt + kq*4];
            {
                int nt=row>>3;
                int sg=(((ks^nt)&3)^(g>>1))&3;
                int bb=((nt*4+ks)*32+4*g)*2 + kh;
                Bs[bb+((0^sg)<<1)]=f2tf32(bv.x);
                Bs[bb+((1^sg)<<1)]=f2tf32(bv.y);
                Bs[bb+((2^sg)<<1)]=f2tf32(bv.z);
                Bs[bb+((3^sg)<<1)]=f2tf32(bv.w);
            }
        }
        __syncthreads();
#pragma unroll
        for (int ks=0; ks<4; ks++) {
            int sa = lane ^ ((ks^(lane>>3))&3);
            uint32_t afr[2][4];
#pragma unroll
            for (int mt2=0; mt2<2; mt2++) {
                int mt=wm*2+mt2;
                *(uint4*)afr[mt2] = *(const uint4*)&As[((mt*4+ks)*32+sa)*4];
            }
#pragma unroll
            for (int nt2=0; nt2<8; nt2++) {
                int nt=wn*8+nt2;
                int sb = lane ^ ((((ks^nt)&3)^(lane>>3))&3);
                uint32_t bfr[2];
                *(uint2*)bfr = *(const uint2*)&Bs[((nt*4+ks)*32+sb)*2];
                mma_tf32(acc[0][nt2],afr[0],bfr);
                mma_tf32(acc[1][nt2],afr[1],bfr);
            }
        }
        __syncthreads();
    }

    const int gr=lane>>2, gl=lane&3;
#pragma unroll
    for (int mt2=0; mt2<2; mt2++) {
#pragma unroll
        for (int nt2=0; nt2<8; nt2++) {
            int n = n0 + wn*64 + nt2*8 + gl*2;
            float b0=biasv[n], b1=biasv[n+1];
#pragma unroll
            for (int half=0; half<2; half++) {
                int m = m0 + wm*32 + mt2*16 + gr + half*8;
                float v0 = acc[mt2][nt2][half*2+0] + b0;
                float v1 = acc[mt2][nt2][half*2+1] + b1;
                if (MODE==0) {
                    *(float2*)&Cout[(size_t)m*Nn+n] = make_float2(v0,v1);
                } else {
                    int part=n/DIM, rem=n-part*DIM, h=rem>>6, d=rem&63;
                    int bb=m>>9, tok=m&511;
                    size_t o = ((size_t)((bb*NHEAD+h)*NTOK+tok))*HD + d;
                    if (part==0)      *(float2*)&g_q[o]=make_float2(v0*ATTN_SCALE,v1*ATTN_SCALE);
                    else if (part==1) *(float2*)&g_k[o]=make_float2(v0,v1);
                    else              *(float2*)&g_v[o]=make_float2(v0,v1);
                }
            }
        }
    }
}

// ---- TF32 mma flash attention: 128 q-rows/block, 8 warps, 64-key chunks ----
__global__ __launch_bounds__(256,2)
void attn_mma_kernel()
{
    __shared__ uint32_t Qs[8192];    // A-frag tiles (mt=warp, ks=0..7), 32KB
    __shared__ uint32_t KVs[4096];   // B-frag tiles (nt, ks), K/V time-shared, 16KB

    const int tid=threadIdx.x, warp=tid>>5, lane=tid&31, l_l=lane&3;
    const int row0=blockIdx.x*128, h=blockIdx.y, b=blockIdx.z;
    const size_t base = ((size_t)(b*NHEAD+h))*NTOK*HD;
    const int rt = blockIdx.x*8 + warp;

    // Q tile -> A-frag layout
#pragma unroll
    for (int u=0; u<8; u++) {
        int f4=tid+256*u, row=f4>>4, d0=(f4&15)*4;
        float4 q = *(const float4*)&g_q[base + (size_t)(row0+row)*HD + d0];
        int ks=d0>>3, dh=(d0>>2)&1, mt=row>>4, g=row&7, r8=(row>>3)&1;
        int sg=((ks&3)^(g>>1))&3;
        int ab=((mt*8+ks)*32+4*g)*4 + r8 + 2*dh;
        Qs[ab+((0^sg)<<2)]=f2tf32(q.x);
        Qs[ab+((1^sg)<<2)]=f2tf32(q.y);
        Qs[ab+((2^sg)<<2)]=f2tf32(q.z);
        Qs[ab+((3^sg)<<2)]=f2tf32(q.w);
    }

    float oacc[8][4];
#pragma unroll
    for(int i=0;i<8;i++)
#pragma unroll
        for(int j=0;j<4;j++) oacc[i][j]=0.f;
    float s0=0.f, s1=0.f;
    const int srcA = (lane&28)|(l_l>>1);

    for (int ch=0; ch<8; ch++) {
        const int c0=ch*64;
        __syncthreads();                         // prev PV done with KVs

        // K chunk -> B-frag (B=K^T: l=dim&3, g=key&7)
#pragma unroll
        for (int u=0; u<4; u++) {
            int f4=tid+256*u, key=f4>>4, d0=(f4&15)*4;
            float4 kv = *(const float4*)&g_k[base + (size_t)(c0+key)*HD + d0];
            int ks=d0>>3, kh=(d0>>2)&1, nt=key>>3, g=key&7;
            int sg=(((ks^nt)&3)^(g>>1))&3;
            int bb=((nt*8+ks)*32+4*g)*2 + kh;
            KVs[bb+((0^sg)<<1)]=f2tf32(kv.x);
            KVs[bb+((1^sg)<<1)]=f2tf32(kv.y);
            KVs[bb+((2^sg)<<1)]=f2tf32(kv.z);
            KVs[bb+((3^sg)<<1)]=f2tf32(kv.w);
        }
        __syncthreads();

        // S = Q @ K^T (warp: 16 x 64)
        float sf[8][4];
#pragma unroll
        for(int i=0;i<8;i++)
#pragma unroll
            for(int j=0;j<4;j++) sf[i][j]=0.f;
#pragma unroll
        for (int ks=0; ks<8; ks++) {
            int sa = lane ^ (((ks&3)^(lane>>3))&3);
            uint32_t a[4];
            *(uint4*)a = *(const uint4*)&Qs[((warp*8+ks)*32+sa)*4];
#pragma unroll
            for (int nt=0; nt<8; nt++) {
                int sb = lane ^ ((((ks^nt)&3)^(lane>>3))&3);
                uint32_t bb[2];
                *(uint2*)bb = *(const uint2*)&KVs[((nt*8+ks)*32+sb)*2];
                mma_tf32(sf[nt],a,bb);
            }
        }
        __syncthreads();                         // all warps done reading K

        // V chunk -> B-frag (B=V: l=key&3, g=dim&7)
#pragma unroll
        for (int u=0; u<4; u++) {
            int f4=tid+256*u, key=f4>>4, d0=(f4&15)*4;
            float4 vv = *(const float4*)&g_v[base + (size_t)(c0+key)*HD + d0];
            float vq[4]={vv.x,vv.y,vv.z,vv.w};
            int kc=key>>3, lk=key&3, rg=(key>>2)&1, nt=d0>>3;
#pragma unroll
            for (int j=0; j<4; j++) {
                int g=(d0&7)+j;
                int sg=(((kc^nt)&3)^(g>>1))&3;
                KVs[((nt*8+kc)*32 + 4*g + (lk^sg))*2 + rg] = f2tf32(vq[j]);
            }
        }

        // P = exp(S + bias), accumulate row sums (register-only, overlaps fill)
#pragma unroll
        for (int nt=0; nt<8; nt++) {
            float4 bf = *(const float4*)&g_biasp[
                ((((size_t)h*32+rt)*8+ch)*8+nt)*128 + lane*4];
            sf[nt][0]=__expf(sf[nt][0]+bf.x);
            sf[nt][1]=__expf(sf[nt][1]+bf.y);
            sf[nt][2]=__expf(sf[nt][2]+bf.z);
            sf[nt][3]=__expf(sf[nt][3]+bf.w);
            s0 += sf[nt][0]+sf[nt][1];
            s1 += sf[nt][2]+sf[nt][3];
        }
        __syncthreads();                         // V visible

        // O += P @ V  (a-frags from sf via shfl)
#pragma unroll
        for (int kc=0; kc<8; kc++) {
            float c0v=sf[kc][0], c1v=sf[kc][1], c2v=sf[kc][2], c3v=sf[kc][3];
            float s00=__shfl_sync(0xffffffffu,c0v,srcA);
            float s01=__shfl_sync(0xffffffffu,c1v,srcA);
            float s10=__shfl_sync(0xffffffffu,c2v,srcA);
            float s11=__shfl_sync(0xffffffffu,c3v,srcA);
            float t00=__shfl_sync(0xffffffffu,c0v,srcA+2);
            float t01=__shfl_sync(0xffffffffu,c1v,srcA+2);
            float t10=__shfl_sync(0xffffffffu,c2v,srcA+2);
            float t11=__shfl_sync(0xffffffffu,c3v,srcA+2);
            bool odd = l_l & 1;
            uint32_t a[4];
            a[0]=f2tf32(odd?s01:s00); a[1]=f2tf32(odd?s11:s10);
            a[2]=f2tf32(odd?t01:t00); a[3]=f2tf32(odd?t11:t10);
#pragma unroll
            for (int nt=0; nt<8; nt++) {
                int sb = lane ^ ((((kc^nt)&3)^(lane>>3))&3);
                uint32_t bb[2];
                *(uint2*)bb = *(const uint2*)&KVs[((nt*8+kc)*32+sb)*2];
                mma_tf32(oacc[nt],a,bb);
            }
        }
    }

    // finalize: row-sum across the 4 lanes of each group, normalize, store
    s0 += __shfl_xor_sync(0xffffffffu,s0,1);
    s0 += __shfl_xor_sync(0xffffffffu,s0,2);
    s1 += __shfl_xor_sync(0xffffffffu,s1,1);
    s1 += __shfl_xor_sync(0xffffffffu,s1,2);
    float i0=1.f/s0, i1=1.f/s1;
    int rowA = row0 + warp*16 + (lane>>2);
#pragma unroll
    for (int nt=0; nt<8; nt++) {
        int col = h*HD + nt*8 + 2*l_l;
        *(float2*)&g_attnout[((size_t)b*NTOK+rowA)*DIM + col] =
            make_float2(oacc[nt][0]*i0, oacc[nt][1]*i0);
        *(float2*)&g_attnout[((size_t)b*NTOK+rowA+8)*DIM + col] =
            make_float2(oacc[nt][2]*i1, oacc[nt][3]*i1);
    }
}

extern "C" void kernel_launch(void* const* d_in, const int* in_sizes, int n_in,
                              void* d_out, int out_size)
{
    const float* x     = (const float*)d_in[0];
    const float* Wqkv  = (const float*)d_in[1];
    const float* bqkv  = (const float*)d_in[2];
    const float* table = (const float*)d_in[3];
    const int*   idx   = (const int*)  d_in[4];
    const float* Wproj = (const float*)d_in[5];
    const float* bproj = (const float*)d_in[6];
    float* out = (float*)d_out;

    bias_gather_kernel<<<(NTOK*NTOK)/256, 256>>>(table, idx);

    gemm_tf32_kernel<1><<<dim3(QKV_N/128, MTOK/128), 256>>>(
        x, Wqkv, bqkv, nullptr, MTOK, QKV_N, DIM);

    attn_mma_kernel<<<dim3(NTOK/128, NHEAD, NBATCH), 256>>>();

    gemm_tf32_kernel<0><<<dim3(DIM/128, MTOK/128), 256>>>(
        nullptr, Wproj, bproj, out, MTOK, DIM, DIM);
}

// round 6
// speedup vs baseline: 3.6640x; 1.1426x over previous
#include <cuda_runtime.h>
#include <cstdint>

#define NHEAD 12
#define HD 64
#define NTOK 512
#define NBATCH 32
#define DIM 768
#define MTOK (NBATCH*NTOK)
#define QKV_N (3*DIM)
#define ATTN_SCALE 0.125f

__device__ float g_q[(size_t)NBATCH*NHEAD*NTOK*HD];
__device__ float g_k[(size_t)NBATCH*NHEAD*NTOK*HD];
__device__ float g_v[(size_t)NBATCH*NHEAD*NTOK*HD];
__device__ float g_biasp[(size_t)NHEAD*NTOK*NTOK];   // c-frag layout [h][rt][ch][nt][lane][reg]
__device__ float g_attnout[(size_t)MTOK*DIM];

__device__ __forceinline__ uint32_t f2tf32(float x){
    uint32_t r; asm("cvt.rna.tf32.f32 %0, %1;" : "=r"(r) : "f"(x)); return r;
}
__device__ __forceinline__ void mma_tf32(float* c,const uint32_t* a,const uint32_t* b){
    asm volatile("mma.sync.aligned.m16n8k8.row.col.f32.tf32.tf32.f32 "
        "{%0,%1,%2,%3}, {%4,%5,%6,%7}, {%8,%9}, {%0,%1,%2,%3};"
        : "+f"(c[0]),"+f"(c[1]),"+f"(c[2]),"+f"(c[3])
        : "r"(a[0]),"r"(a[1]),"r"(a[2]),"r"(a[3]),"r"(b[0]),"r"(b[1]));
}

// ---- bias gather into c-fragment layout ----
__global__ void bias_gather_kernel(const float* __restrict__ table,
                                   const int* __restrict__ idx)
{
    int e = blockIdx.x*256 + threadIdx.x;       // 0..262143
    int rt=e>>13, kt=(e>>10)&7, nt=(e>>7)&7, lane=(e>>2)&31, reg=e&3;
    int g=lane>>2, l=lane&3;
    int row = rt*16 + g + 8*(reg>>1);
    int col = kt*64 + nt*8 + 2*l + (reg&1);
    int id = idx[row*NTOK + col];
    const float* t = table + (size_t)id*NHEAD;
#pragma unroll
    for (int h=0; h<NHEAD; h++)
        g_biasp[(size_t)h*262144 + e] = t[h];
}

// ---- TF32 GEMM, double-buffered: C = A @ Bw^T + bias ----
template<int MODE>
__global__ __launch_bounds__(256,2)
void gemm_tf32_kernel(const float* __restrict__ Ain,const float* __restrict__ Bw,
                      const float* __restrict__ biasv,float* __restrict__ Cout,
                      int M,int Nn,int K)
{
    __shared__ uint32_t As[2][4096];
    __shared__ uint32_t Bs[2][4096];
    const float* A = (MODE==0) ? g_attnout : Ain;
    const int tid=threadIdx.x, warp=tid>>5, lane=tid&31;
    const int wm=warp&3, wn=warp>>2;
    const int m0=blockIdx.y*128, n0=blockIdx.x*128;
    const int nT = K >> 5;

    float acc[2][8][4];
#pragma unroll
    for(int i=0;i<2;i++)
#pragma unroll
        for(int j=0;j<8;j++)
#pragma unroll
            for(int r=0;r<4;r++) acc[i][j][r]=0.f;

    float4 av[4], bv[4];

    // prologue: load tile 0 into regs, store to buffer 0
#pragma unroll
    for (int u=0; u<4; u++) {
        int f4=tid+256*u, row=f4>>3, kq=f4&7;
        av[u] = *(const float4*)&A [(size_t)(m0+row)*K + kq*4];
        bv[u] = *(const float4*)&Bw[(size_t)(n0+row)*K + kq*4];
    }
#pragma unroll
    for (int u=0; u<4; u++) {
        int f4=tid+256*u, row=f4>>3, kq=f4&7, ks=kq>>1, kh=kq&1, g=row&7;
        {
            int mt=row>>4, r8=(row>>3)&1, sg=(ks^(g>>1))&3;
            int ab=((mt*4+ks)*32+4*g)*4 + r8 + 2*kh;
            As[0][ab+((0^sg)<<2)]=f2tf32(av[u].x);
            As[0][ab+((1^sg)<<2)]=f2tf32(av[u].y);
            As[0][ab+((2^sg)<<2)]=f2tf32(av[u].z);
            As[0][ab+((3^sg)<<2)]=f2tf32(av[u].w);
        }
        {
            int nt=row>>3, sg=(((ks^nt)&3)^(g>>1))&3;
            int bb=((nt*4+ks)*32+4*g)*2 + kh;
            Bs[0][bb+((0^sg)<<1)]=f2tf32(bv[u].x);
            Bs[0][bb+((1^sg)<<1)]=f2tf32(bv[u].y);
            Bs[0][bb+((2^sg)<<1)]=f2tf32(bv[u].z);
            Bs[0][bb+((3^sg)<<1)]=f2tf32(bv[u].w);
        }
    }
    __syncthreads();

    for (int t=0; t<nT; t++) {
        const int cur = t&1, nxt = cur^1;
        const bool hasNext = (t+1 < nT);
        if (hasNext) {
            int kt=(t+1)<<5;
#pragma unroll
            for (int u=0; u<4; u++) {
                int f4=tid+256*u, row=f4>>3, kq=f4&7;
                av[u] = *(const float4*)&A [(size_t)(m0+row)*K + kt + kq*4];
                bv[u] = *(const float4*)&Bw[(size_t)(n0+row)*K + kt + kq*4];
            }
        }
        // compute current tile
#pragma unroll
        for (int ks=0; ks<4; ks++) {
            int sa = lane ^ ((ks^(lane>>3))&3);
            uint32_t afr[2][4];
#pragma unroll
            for (int mt2=0; mt2<2; mt2++) {
                int mt=wm*2+mt2;
                *(uint4*)afr[mt2] = *(const uint4*)&As[cur][((mt*4+ks)*32+sa)*4];
            }
#pragma unroll
            for (int nt2=0; nt2<8; nt2++) {
                int nt=wn*8+nt2;
                int sb = lane ^ ((((ks^nt)&3)^(lane>>3))&3);
                uint32_t bfr[2];
                *(uint2*)bfr = *(const uint2*)&Bs[cur][((nt*4+ks)*32+sb)*2];
                mma_tf32(acc[0][nt2],afr[0],bfr);
                mma_tf32(acc[1][nt2],afr[1],bfr);
            }
        }
        if (hasNext) {
#pragma unroll
            for (int u=0; u<4; u++) {
                int f4=tid+256*u, row=f4>>3, kq=f4&7, ks=kq>>1, kh=kq&1, g=row&7;
                {
                    int mt=row>>4, r8=(row>>3)&1, sg=(ks^(g>>1))&3;
                    int ab=((mt*4+ks)*32+4*g)*4 + r8 + 2*kh;
                    As[nxt][ab+((0^sg)<<2)]=f2tf32(av[u].x);
                    As[nxt][ab+((1^sg)<<2)]=f2tf32(av[u].y);
                    As[nxt][ab+((2^sg)<<2)]=f2tf32(av[u].z);
                    As[nxt][ab+((3^sg)<<2)]=f2tf32(av[u].w);
                }
                {
                    int nt=row>>3, sg=(((ks^nt)&3)^(g>>1))&3;
                    int bb=((nt*4+ks)*32+4*g)*2 + kh;
                    Bs[nxt][bb+((0^sg)<<1)]=f2tf32(bv[u].x);
                    Bs[nxt][bb+((1^sg)<<1)]=f2tf32(bv[u].y);
                    Bs[nxt][bb+((2^sg)<<1)]=f2tf32(bv[u].z);
                    Bs[nxt][bb+((3^sg)<<1)]=f2tf32(bv[u].w);
                }
            }
        }
        __syncthreads();
    }

    const int gr=lane>>2, gl=lane&3;
#pragma unroll
    for (int mt2=0; mt2<2; mt2++) {
#pragma unroll
        for (int nt2=0; nt2<8; nt2++) {
            int n = n0 + wn*64 + nt2*8 + gl*2;
            float b0=biasv[n], b1=biasv[n+1];
#pragma unroll
            for (int half=0; half<2; half++) {
                int m = m0 + wm*32 + mt2*16 + gr + half*8;
                float v0 = acc[mt2][nt2][half*2+0] + b0;
                float v1 = acc[mt2][nt2][half*2+1] + b1;
                if (MODE==0) {
                    *(float2*)&Cout[(size_t)m*Nn+n] = make_float2(v0,v1);
                } else {
                    int part=n/DIM, rem=n-part*DIM, h=rem>>6, d=rem&63;
                    int bb=m>>9, tok=m&511;
                    size_t o = ((size_t)((bb*NHEAD+h)*NTOK+tok))*HD + d;
                    if (part==0)      *(float2*)&g_q[o]=make_float2(v0*ATTN_SCALE,v1*ATTN_SCALE);
                    else if (part==1) *(float2*)&g_k[o]=make_float2(v0,v1);
                    else              *(float2*)&g_v[o]=make_float2(v0,v1);
                }
            }
        }
    }
}

// ---- TF32 mma flash attention (unchanged from R5) ----
__global__ __launch_bounds__(256,2)
void attn_mma_kernel()
{
    __shared__ uint32_t Qs[8192];
    __shared__ uint32_t KVs[4096];

    const int tid=threadIdx.x, warp=tid>>5, lane=tid&31, l_l=lane&3;
    const int row0=blockIdx.x*128, h=blockIdx.y, b=blockIdx.z;
    const size_t base = ((size_t)(b*NHEAD+h))*NTOK*HD;
    const int rt = blockIdx.x*8 + warp;

#pragma unroll
    for (int u=0; u<8; u++) {
        int f4=tid+256*u, row=f4>>4, d0=(f4&15)*4;
        float4 q = *(const float4*)&g_q[base + (size_t)(row0+row)*HD + d0];
        int ks=d0>>3, dh=(d0>>2)&1, mt=row>>4, g=row&7, r8=(row>>3)&1;
        int sg=((ks&3)^(g>>1))&3;
        int ab=((mt*8+ks)*32+4*g)*4 + r8 + 2*dh;
        Qs[ab+((0^sg)<<2)]=f2tf32(q.x);
        Qs[ab+((1^sg)<<2)]=f2tf32(q.y);
        Qs[ab+((2^sg)<<2)]=f2tf32(q.z);
        Qs[ab+((3^sg)<<2)]=f2tf32(q.w);
    }

    float oacc[8][4];
#pragma unroll
    for(int i=0;i<8;i++)
#pragma unroll
        for(int j=0;j<4;j++) oacc[i][j]=0.f;
    float s0=0.f, s1=0.f;
    const int srcA = (lane&28)|(l_l>>1);

    for (int ch=0; ch<8; ch++) {
        const int c0=ch*64;
        __syncthreads();

#pragma unroll
        for (int u=0; u<4; u++) {
            int f4=tid+256*u, key=f4>>4, d0=(f4&15)*4;
            float4 kv = *(const float4*)&g_k[base + (size_t)(c0+key)*HD + d0];
            int ks=d0>>3, kh=(d0>>2)&1, nt=key>>3, g=key&7;
            int sg=(((ks^nt)&3)^(g>>1))&3;
            int bb=((nt*8+ks)*32+4*g)*2 + kh;
            KVs[bb+((0^sg)<<1)]=f2tf32(kv.x);
            KVs[bb+((1^sg)<<1)]=f2tf32(kv.y);
            KVs[bb+((2^sg)<<1)]=f2tf32(kv.z);
            KVs[bb+((3^sg)<<1)]=f2tf32(kv.w);
        }
        __syncthreads();

        float sf[8][4];
#pragma unroll
        for(int i=0;i<8;i++)
#pragma unroll
            for(int j=0;j<4;j++) sf[i][j]=0.f;
#pragma unroll
        for (int ks=0; ks<8; ks++) {
            int sa = lane ^ (((ks&3)^(lane>>3))&3);
            uint32_t a[4];
            *(uint4*)a = *(const uint4*)&Qs[((warp*8+ks)*32+sa)*4];
#pragma unroll
            for (int nt=0; nt<8; nt++) {
                int sb = lane ^ ((((ks^nt)&3)^(lane>>3))&3);
                uint32_t bb[2];
                *(uint2*)bb = *(const uint2*)&KVs[((nt*8+ks)*32+sb)*2];
                mma_tf32(sf[nt],a,bb);
            }
        }
        __syncthreads();

#pragma unroll
        for (int u=0; u<4; u++) {
            int f4=tid+256*u, key=f4>>4, d0=(f4&15)*4;
            float4 vv = *(const float4*)&g_v[base + (size_t)(c0+key)*HD + d0];
            float vq[4]={vv.x,vv.y,vv.z,vv.w};
            int kc=key>>3, lk=key&3, rg=(key>>2)&1, nt=d0>>3;
#pragma unroll
            for (int j=0; j<4; j++) {
                int g=(d0&7)+j;
                int sg=(((kc^nt)&3)^(g>>1))&3;
                KVs[((nt*8+kc)*32 + 4*g + (lk^sg))*2 + rg] = f2tf32(vq[j]);
            }
        }

#pragma unroll
        for (int nt=0; nt<8; nt++) {
            float4 bf = *(const float4*)&g_biasp[
                ((((size_t)h*32+rt)*8+ch)*8+nt)*128 + lane*4];
            sf[nt][0]=__expf(sf[nt][0]+bf.x);
            sf[nt][1]=__expf(sf[nt][1]+bf.y);
            sf[nt][2]=__expf(sf[nt][2]+bf.z);
            sf[nt][3]=__expf(sf[nt][3]+bf.w);
            s0 += sf[nt][0]+sf[nt][1];
            s1 += sf[nt][2]+sf[nt][3];
        }
        __syncthreads();

#pragma unroll
        for (int kc=0; kc<8; kc++) {
            float c0v=sf[kc][0], c1v=sf[kc][1], c2v=sf[kc][2], c3v=sf[kc][3];
            float s00=__shfl_sync(0xffffffffu,c0v,srcA);
            float s01=__shfl_sync(0xffffffffu,c1v,srcA);
            float s10=__shfl_sync(0xffffffffu,c2v,srcA);
            float s11=__shfl_sync(0xffffffffu,c3v,srcA);
            float t00=__shfl_sync(0xffffffffu,c0v,srcA+2);
            float t01=__shfl_sync(0xffffffffu,c1v,srcA+2);
            float t10=__shfl_sync(0xffffffffu,c2v,srcA+2);
            float t11=__shfl_sync(0xffffffffu,c3v,srcA+2);
            bool odd = l_l & 1;
            uint32_t a[4];
            a[0]=f2tf32(odd?s01:s00); a[1]=f2tf32(odd?s11:s10);
            a[2]=f2tf32(odd?t01:t00); a[3]=f2tf32(odd?t11:t10);
#pragma unroll
            for (int nt=0; nt<8; nt++) {
                int sb = lane ^ ((((kc^nt)&3)^(lane>>3))&3);
                uint32_t bb[2];
                *(uint2*)bb = *(const uint2*)&KVs[((nt*8+kc)*32+sb)*2];
                mma_tf32(oacc[nt],a,bb);
            }
        }
    }

    s0 += __shfl_xor_sync(0xffffffffu,s0,1);
    s0 += __shfl_xor_sync(0xffffffffu,s0,2);
    s1 += __shfl_xor_sync(0xffffffffu,s1,1);
    s1 += __shfl_xor_sync(0xffffffffu,s1,2);
    float i0=1.f/s0, i1=1.f/s1;
    int rowA = row0 + warp*16 + (lane>>2);
#pragma unroll
    for (int nt=0; nt<8; nt++) {
        int col = h*HD + nt*8 + 2*l_l;
        *(float2*)&g_attnout[((size_t)b*NTOK+rowA)*DIM + col] =
            make_float2(oacc[nt][0]*i0, oacc[nt][1]*i0);
        *(float2*)&g_attnout[((size_t)b*NTOK+rowA+8)*DIM + col] =
            make_float2(oacc[nt][2]*i1, oacc[nt][3]*i1);
    }
}

extern "C" void kernel_launch(void* const* d_in, const int* in_sizes, int n_in,
                              void* d_out, int out_size)
{
    const float* x     = (const float*)d_in[0];
    const float* Wqkv  = (const float*)d_in[1];
    const float* bqkv  = (const float*)d_in[2];
    const float* table = (const float*)d_in[3];
    const int*   idx   = (const int*)  d_in[4];
    const float* Wproj = (const float*)d_in[5];
    const float* bproj = (const float*)d_in[6];
    float* out = (float*)d_out;

    bias_gather_kernel<<<(NTOK*NTOK)/256, 256>>>(table, idx);

    gemm_tf32_kernel<1><<<dim3(QKV_N/128, MTOK/128), 256>>>(
        x, Wqkv, bqkv, nullptr, MTOK, QKV_N, DIM);

    attn_mma_kernel<<<dim3(NTOK/128, NHEAD, NBATCH), 256>>>();

    gemm_tf32_kernel<0><<<dim3(DIM/128, MTOK/128), 256>>>(
        nullptr, Wproj, bproj, out, MTOK, DIM, DIM);
}